// round 9
// baseline (speedup 1.0000x reference)
#include <cuda_runtime.h>
#include <math.h>

// ---------------------------------------------------------------------------
// Problem constants
//   N_LAYER=6, N_HEAD=16, D_MODEL=1024, D_HEAD=64, D_INNER=4096,
//   N_TOKEN=32000, BSZ=4, QLEN=512, MLEN=512, KLEN=1024
// ---------------------------------------------------------------------------

#define NLYR   6
#define BSZ_   4
#define QLEN_  512
#define KLEN_  1024
#define DMOD   1024
#define NHEAD  16
#define DHEAD  64
#define DINNER 4096
#define VOCAB  32000
#define NROWS  (BSZ_ * QLEN_)      /* 2048 */
#define NCROWS (BSZ_ * KLEN_)      /* 4096 */

// ---------------------------------------------------------------------------
// Scratch (static device globals — allocation-free)
// ---------------------------------------------------------------------------
__device__ float g_x    [NROWS  * DMOD];          // 8  MB  activations
__device__ float g_xcat [NCROWS * DMOD];          // 16 MB  [mem ; x]
__device__ float g_q    [NROWS  * DMOD];          // 8  MB
__device__ float g_kv   [NCROWS * 2 * DMOD];      // 32 MB
__device__ float g_rk   [KLEN_  * DMOD];          // 4  MB
__device__ float g_pos  [KLEN_  * DMOD];          // 4  MB
__device__ float g_vec  [NROWS  * DMOD];          // 8  MB
__device__ float g_tmp  [NROWS  * DMOD];          // 8  MB
__device__ float g_ffh  [NROWS  * DINNER];        // 32 MB
__device__ float g_lgt  [(size_t)NROWS * VOCAB];  // 262 MB

// ---------------------------------------------------------------------------
// Embedding gather: x[row] = emb[data[row]]
// ---------------------------------------------------------------------------
__global__ __launch_bounds__(256) void embed_kernel(
    const int* __restrict__ data, const float* __restrict__ emb,
    float* __restrict__ x)
{
    int row = blockIdx.x;
    int tok = data[row];
    const float4* src = (const float4*)(emb + (size_t)tok * DMOD);
    float4*       dst = (float4*)(x + (size_t)row * DMOD);
    dst[threadIdx.x] = src[threadIdx.x];
}

// ---------------------------------------------------------------------------
// Positional embedding: pos[p, f] = sin((1023-p)*invf), pos[p, 512+f] = cos(...)
// ---------------------------------------------------------------------------
__global__ __launch_bounds__(512) void posemb_kernel(float* __restrict__ pos)
{
    int p = blockIdx.x;
    int f = threadIdx.x;                       // 0..511
    double invf = exp(-((double)(2 * f) / 1024.0) * log(10000.0));
    float ang = (float)((double)(KLEN_ - 1 - p) * invf);
    pos[(size_t)p * DMOD + f]        = sinf(ang);
    pos[(size_t)p * DMOD + 512 + f]  = cosf(ang);
}

// ---------------------------------------------------------------------------
// Concat: xcat[b, j] = j<512 ? mem[b, j] : x[b, j-512]
// ---------------------------------------------------------------------------
__global__ __launch_bounds__(256) void concat_kernel(
    const float* __restrict__ mem, const float* __restrict__ x,
    float* __restrict__ xc)
{
    int row = blockIdx.x;                      // b*1024 + j
    int b = row >> 10, j = row & 1023;
    const float4* src = (j < QLEN_)
        ? (const float4*)(mem + ((size_t)b * QLEN_ + j) * DMOD)
        : (const float4*)(x   + ((size_t)b * QLEN_ + (j - QLEN_)) * DMOD);
    float4* dst = (float4*)(xc + (size_t)row * DMOD);
    dst[threadIdx.x] = src[threadIdx.x];
}

// ---------------------------------------------------------------------------
// SGEMM: C[M,N] = A[M,K] @ B  (BT=false: B is [K,N]; BT=true: B is [N,K], C=A@B^T)
// 128x128 block tile, BK=8, 256 threads, 8x8 microtile, reg-prefetch pipeline.
// Requires M%128==0, N%128==0, K%8==0 (true for every call here).
// EPI: 0 = none, 1 = +bias, 2 = relu(+bias)
// ---------------------------------------------------------------------------
template<int EPI, bool BT>
__global__ __launch_bounds__(256, 2) void sgemm(
    const float* __restrict__ A, const float* __restrict__ Bm,
    const float* __restrict__ bias, float* __restrict__ C,
    int M, int N, int K)
{
    __shared__ float As[8][128];
    __shared__ float Bs[8][128];

    const int tid = threadIdx.x;
    const int bm = blockIdx.y << 7;
    const int bn = blockIdx.x << 7;
    const int tx = tid & 15, ty = tid >> 4;

    // A loader: 128 rows x 8 k, 2 threads/row
    const int arow = tid >> 1, acol = (tid & 1) << 2;
    const float* Ap = A + (size_t)(bm + arow) * K + acol;

    // B loader
    int brow, bcol;
    const float* Bp;
    if (BT) { brow = tid >> 1; bcol = (tid & 1) << 2;
              Bp = Bm + (size_t)(bn + brow) * K + bcol; }
    else    { brow = tid >> 5; bcol = (tid & 31) << 2;
              Bp = Bm + (size_t)brow * N + bn + bcol; }

    float4 aR = *(const float4*)Ap;
    float4 bR = *(const float4*)Bp;

    float acc[8][8];
#pragma unroll
    for (int r = 0; r < 8; r++)
#pragma unroll
        for (int c = 0; c < 8; c++) acc[r][c] = 0.f;

    const int nk = K >> 3;
    for (int kt = 0; kt < nk; kt++) {
        As[acol + 0][arow] = aR.x;
        As[acol + 1][arow] = aR.y;
        As[acol + 2][arow] = aR.z;
        As[acol + 3][arow] = aR.w;
        if (BT) {
            Bs[bcol + 0][brow] = bR.x;
            Bs[bcol + 1][brow] = bR.y;
            Bs[bcol + 2][brow] = bR.z;
            Bs[bcol + 3][brow] = bR.w;
        } else {
            *(float4*)&Bs[brow][bcol] = bR;
        }
        __syncthreads();

        if (kt + 1 < nk) {
            aR = *(const float4*)(Ap + (size_t)(kt + 1) * 8);
            bR = BT ? *(const float4*)(Bp + (size_t)(kt + 1) * 8)
                    : *(const float4*)(Bp + (size_t)(kt + 1) * 8 * N);
        }

#pragma unroll
        for (int k = 0; k < 8; k++) {
            float4 a0 = *(const float4*)&As[k][ty << 3];
            float4 a1 = *(const float4*)&As[k][(ty << 3) + 4];
            float4 b0 = *(const float4*)&Bs[k][tx << 3];
            float4 b1 = *(const float4*)&Bs[k][(tx << 3) + 4];
            float av[8] = {a0.x, a0.y, a0.z, a0.w, a1.x, a1.y, a1.z, a1.w};
            float bv[8] = {b0.x, b0.y, b0.z, b0.w, b1.x, b1.y, b1.z, b1.w};
#pragma unroll
            for (int r = 0; r < 8; r++)
#pragma unroll
                for (int c = 0; c < 8; c++) acc[r][c] += av[r] * bv[c];
        }
        __syncthreads();
    }

#pragma unroll
    for (int r = 0; r < 8; r++) {
        float* Cr = C + (size_t)(bm + (ty << 3) + r) * N + bn + (tx << 3);
#pragma unroll
        for (int c = 0; c < 8; c++) {
            float v = acc[r][c];
            if (EPI >= 1) v += bias[bn + (tx << 3) + c];
            if (EPI == 2) v = v > 0.f ? v : 0.f;
            Cr[c] = v;
        }
    }
}

// ---------------------------------------------------------------------------
// Fused relative attention.
// Grid: (32 i-tiles, 16 heads, 4 batches), 256 threads, dynamic smem.
//
// For unmasked positions (j <= i+512) the Transformer-XL rel_shift reduces to
//   BD[i, j] = dot(q_i + br, rk[j - i + 511])
// (verified against the exact pad/reshape/slice index algebra; masked region
// never survives the restricted softmax, which is exactly equivalent to the
// reference's -1e30 mask).
// ---------------------------------------------------------------------------
#define ATTN_SP   17                                   /* smem score pitch   */
#define ATTN_SMEM ((KLEN_*ATTN_SP + 1024 + 1024 + 4096 + 16) * 4)

__global__ __launch_bounds__(256) void attn_kernel(
    const float* __restrict__ q,  const float* __restrict__ kv,
    const float* __restrict__ rk, const float* __restrict__ bw,
    const float* __restrict__ br, float* __restrict__ vec)
{
    extern __shared__ float sm[];
    float* s    = sm;                          // [1024][17]
    float* qw   = sm + KLEN_ * ATTN_SP;        // [16][64]
    float* qr   = qw + 1024;                   // [16][64]
    float* red  = qr + 1024;                   // [4][16][64]
    float* sinv = red + 4096;                  // [16]

    const int itile = blockIdx.x, n = blockIdx.y, b = blockIdx.z;
    const int tid = threadIdx.x;
    const int i0 = itile << 4;
    const int cmax = i0 + 528;                 // max key count in this tile (<=1024)

    // load 16 query rows (+ biases)
    for (int u = tid; u < 1024; u += 256) {
        int i = u >> 6, d = u & 63;
        float qv = q[((size_t)(b * QLEN_ + i0 + i) << 10) + n * 64 + d];
        qw[u] = qv + bw[n * 64 + d];
        qr[u] = qv + br[n * 64 + d];
    }
    __syncthreads();

    // ---- AC: s[j][i] = dot(qw_i, k_j) --------------------------------------
    for (int j = tid; j < cmax; j += 256) {
        const float4* kp = (const float4*)(kv + ((size_t)(b * KLEN_ + j) << 11) + n * 64);
        float4 kr[16];
#pragma unroll
        for (int u = 0; u < 16; u++) kr[u] = kp[u];
#pragma unroll
        for (int i = 0; i < 16; i++) {
            const float4* qp = (const float4*)(qw + (i << 6));
            float acc = 0.f;
#pragma unroll
            for (int u = 0; u < 16; u++) {
                float4 a = qp[u];
                acc += a.x * kr[u].x + a.y * kr[u].y + a.z * kr[u].z + a.w * kr[u].w;
            }
            s[j * ATTN_SP + i] = acc;
        }
    }
    __syncthreads();

    // ---- BD: s[jr + iglob - 511][i] += dot(qr_i, rk_jr) --------------------
    for (int jr = tid; jr < KLEN_; jr += 256) {
        const float4* rp = (const float4*)(rk + ((size_t)jr << 10) + n * 64);
        float4 rr[16];
#pragma unroll
        for (int u = 0; u < 16; u++) rr[u] = rp[u];
#pragma unroll
        for (int i = 0; i < 16; i++) {
            int j = jr + (i0 + i) - 511;       // always < 1024 and < cmax
            if (j >= 0) {
                const float4* qp = (const float4*)(qr + (i << 6));
                float acc = 0.f;
#pragma unroll
                for (int u = 0; u < 16; u++) {
                    float4 a = qp[u];
                    acc += a.x * rr[u].x + a.y * rr[u].y + a.z * rr[u].z + a.w * rr[u].w;
                }
                s[j * ATTN_SP + i] += acc;
            }
        }
    }
    __syncthreads();

    // ---- softmax over j in [0, i+513); store unnormalized p, keep 1/sum ----
    {
        int wid = tid >> 5, lane = tid & 31;
        for (int i = wid; i < 16; i += 8) {
            int count = i0 + i + 513;
            float m = -1e30f;
            for (int j = lane; j < count; j += 32)
                m = fmaxf(m, s[j * ATTN_SP + i]);
#pragma unroll
            for (int o = 16; o; o >>= 1)
                m = fmaxf(m, __shfl_xor_sync(0xffffffffu, m, o));
            float sum = 0.f;
            for (int j = lane; j < count; j += 32) {
                float p = expf((s[j * ATTN_SP + i] - m) * 0.125f);
                s[j * ATTN_SP + i] = p;
                sum += p;
            }
#pragma unroll
            for (int o = 16; o; o >>= 1)
                sum += __shfl_xor_sync(0xffffffffu, sum, o);
            if (lane == 0) sinv[i] = 1.f / sum;
            for (int j = count + lane; j < cmax; j += 32)
                s[j * ATTN_SP + i] = 0.f;      // zero masked tail
        }
    }
    __syncthreads();

    // ---- vec[i, d] = (sum_j p[i,j] * v[j, d]) * sinv[i] ---------------------
    {
        int d = tid & 63, g = tid >> 6;        // 4 groups of 64
        float acc[16];
#pragma unroll
        for (int i = 0; i < 16; i++) acc[i] = 0.f;
        for (int j = g; j < cmax; j += 4) {
            float vv = kv[((size_t)(b * KLEN_ + j) << 11) + 1024 + n * 64 + d];
#pragma unroll
            for (int i = 0; i < 16; i++)
                acc[i] += s[j * ATTN_SP + i] * vv;
        }
#pragma unroll
        for (int i = 0; i < 16; i++) red[((g << 4) + i) * 64 + d] = acc[i];
        __syncthreads();
        if (g == 0) {
#pragma unroll
            for (int i = 0; i < 16; i++) {
                float r0 = red[i * 64 + d] + red[(16 + i) * 64 + d]
                         + red[(32 + i) * 64 + d] + red[(48 + i) * 64 + d];
                vec[((size_t)(b * QLEN_ + i0 + i) << 10) + n * 64 + d] = r0 * sinv[i];
            }
        }
    }
}

// ---------------------------------------------------------------------------
// x = LayerNorm(x + y) * g + b   (population variance, eps=1e-5)
// ---------------------------------------------------------------------------
__global__ __launch_bounds__(256) void add_ln_kernel(
    float* __restrict__ x, const float* __restrict__ y,
    const float* __restrict__ g, const float* __restrict__ bb)
{
    int row = blockIdx.x, tid = threadIdx.x;
    float* xr = x + (size_t)row * DMOD;
    const float* yr = y + (size_t)row * DMOD;
    float v[4];
    float s = 0.f, sq = 0.f;
#pragma unroll
    for (int u = 0; u < 4; u++) {
        int idx = tid + (u << 8);
        v[u] = xr[idx] + yr[idx];
        s += v[u]; sq += v[u] * v[u];
    }
#pragma unroll
    for (int o = 16; o; o >>= 1) {
        s  += __shfl_xor_sync(0xffffffffu, s,  o);
        sq += __shfl_xor_sync(0xffffffffu, sq, o);
    }
    __shared__ float ws[8], wq[8];
    if ((tid & 31) == 0) { ws[tid >> 5] = s; wq[tid >> 5] = sq; }
    __syncthreads();
    s = 0.f; sq = 0.f;
#pragma unroll
    for (int u = 0; u < 8; u++) { s += ws[u]; sq += wq[u]; }
    float mu   = s * (1.f / DMOD);
    float var  = sq * (1.f / DMOD) - mu * mu;
    float rstd = rsqrtf(var + 1e-5f);
#pragma unroll
    for (int u = 0; u < 4; u++) {
        int idx = tid + (u << 8);
        xr[idx] = (v[u] - mu) * rstd * g[idx] + bb[idx];
    }
}

// ---------------------------------------------------------------------------
// NLL: out[row] = -(logits[row, tgt] - logsumexp(logits[row, :]))
// ---------------------------------------------------------------------------
__global__ __launch_bounds__(256) void nll_kernel(
    const float* __restrict__ logits, const int* __restrict__ target,
    float* __restrict__ out)
{
    int row = blockIdx.x, tid = threadIdx.x;
    const float* lr = logits + (size_t)row * VOCAB;

    float m = -1e30f;
    for (int j = tid; j < VOCAB; j += 256) m = fmaxf(m, lr[j]);
#pragma unroll
    for (int o = 16; o; o >>= 1) m = fmaxf(m, __shfl_xor_sync(0xffffffffu, m, o));
    __shared__ float wm[8];
    if ((tid & 31) == 0) wm[tid >> 5] = m;
    __syncthreads();
#pragma unroll
    for (int u = 0; u < 8; u++) m = fmaxf(m, wm[u]);

    float s = 0.f;
    for (int j = tid; j < VOCAB; j += 256) s += expf(lr[j] - m);
#pragma unroll
    for (int o = 16; o; o >>= 1) s += __shfl_xor_sync(0xffffffffu, s, o);
    __shared__ float wsum[8];
    if ((tid & 31) == 0) wsum[tid >> 5] = s;
    __syncthreads();

    if (tid == 0) {
        float tot = 0.f;
#pragma unroll
        for (int u = 0; u < 8; u++) tot += wsum[u];
        out[row] = -(lr[target[row]] - m - logf(tot));
    }
}

// ---------------------------------------------------------------------------
// Orchestration
// ---------------------------------------------------------------------------
extern "C" void kernel_launch(void* const* d_in, const int* in_sizes, int n_in,
                              void* d_out, int out_size)
{
    const int*   data   = (const int*)  d_in[0];
    const int*   target = (const int*)  d_in[1];
    const float* memory = (const float*)d_in[2];
    const float* emb    = (const float*)d_in[3];
    const float* Wq     = (const float*)d_in[4];
    const float* Wkv    = (const float*)d_in[5];
    const float* Wr     = (const float*)d_in[6];
    const float* Wo     = (const float*)d_in[7];
    const float* W1     = (const float*)d_in[8];
    const float* b1     = (const float*)d_in[9];
    const float* W2     = (const float*)d_in[10];
    const float* b2     = (const float*)d_in[11];
    const float* g1     = (const float*)d_in[12];
    const float* be1    = (const float*)d_in[13];
    const float* g2     = (const float*)d_in[14];
    const float* be2    = (const float*)d_in[15];
    const float* bw     = (const float*)d_in[16];
    const float* brr    = (const float*)d_in[17];
    float* out = (float*)d_out;

    float *x, *xc, *qb, *kvb, *rkb, *pos, *vecb, *tmp, *ffh, *lg;
    cudaGetSymbolAddress((void**)&x,    g_x);
    cudaGetSymbolAddress((void**)&xc,   g_xcat);
    cudaGetSymbolAddress((void**)&qb,   g_q);
    cudaGetSymbolAddress((void**)&kvb,  g_kv);
    cudaGetSymbolAddress((void**)&rkb,  g_rk);
    cudaGetSymbolAddress((void**)&pos,  g_pos);
    cudaGetSymbolAddress((void**)&vecb, g_vec);
    cudaGetSymbolAddress((void**)&tmp,  g_tmp);
    cudaGetSymbolAddress((void**)&ffh,  g_ffh);
    cudaGetSymbolAddress((void**)&lg,   g_lgt);

    cudaFuncSetAttribute(attn_kernel,
                         cudaFuncAttributeMaxDynamicSharedMemorySize, ATTN_SMEM);

    embed_kernel <<<NROWS, 256>>>(data, emb, x);
    posemb_kernel<<<KLEN_, 512>>>(pos);

    for (int l = 0; l < NLYR; l++) {
        const float* memL = memory + (size_t)l * BSZ_ * QLEN_ * DMOD;

        concat_kernel<<<NCROWS, 256>>>(memL, x, xc);

        // q = x @ Wq[l]                          [2048,1024] x [1024,1024]
        sgemm<0, false><<<dim3(8, 16), 256>>>(
            x, Wq + (size_t)l * DMOD * DMOD, nullptr, qb, NROWS, DMOD, DMOD);
        // kv = xcat @ Wkv[l]                     [4096,1024] x [1024,2048]
        sgemm<0, false><<<dim3(16, 32), 256>>>(
            xc, Wkv + (size_t)l * DMOD * 2 * DMOD, nullptr, kvb, NCROWS, 2 * DMOD, DMOD);
        // rk = pos @ Wr[l]                       [1024,1024] x [1024,1024]
        sgemm<0, false><<<dim3(8, 8), 256>>>(
            pos, Wr + (size_t)l * DMOD * DMOD, nullptr, rkb, KLEN_, DMOD, DMOD);

        attn_kernel<<<dim3(32, 16, 4), 256, ATTN_SMEM>>>(qb, kvb, rkb, bw, brr, vecb);

        // attn_out = vec @ Wo[l]
        sgemm<0, false><<<dim3(8, 16), 256>>>(
            vecb, Wo + (size_t)l * DMOD * DMOD, nullptr, tmp, NROWS, DMOD, DMOD);
        add_ln_kernel<<<NROWS, 256>>>(x, tmp, g1 + l * DMOD, be1 + l * DMOD);

        // ff = relu(x @ W1 + b1) @ W2 + b2
        sgemm<2, false><<<dim3(32, 16), 256>>>(
            x, W1 + (size_t)l * DMOD * DINNER, b1 + (size_t)l * DINNER,
            ffh, NROWS, DINNER, DMOD);
        sgemm<1, false><<<dim3(8, 16), 256>>>(
            ffh, W2 + (size_t)l * DINNER * DMOD, b2 + (size_t)l * DMOD,
            tmp, NROWS, DMOD, DINNER);
        add_ln_kernel<<<NROWS, 256>>>(x, tmp, g2 + l * DMOD, be2 + l * DMOD);
    }

    // logits = x @ emb^T   [2048,1024] x [32000,1024]^T
    sgemm<0, true><<<dim3(VOCAB / 128, 16), 256>>>(
        x, emb, nullptr, lg, NROWS, VOCAB, DMOD);

    nll_kernel<<<NROWS, 256>>>(lg, target, out);
}

// round 10
// speedup vs baseline: 1.0598x; 1.0598x over previous
#include <cuda_runtime.h>
#include <math.h>

// ---------------------------------------------------------------------------
// Problem constants
//   N_LAYER=6, N_HEAD=16, D_MODEL=1024, D_HEAD=64, D_INNER=4096,
//   N_TOKEN=32000, BSZ=4, QLEN=512, MLEN=512, KLEN=1024
// ---------------------------------------------------------------------------

#define NLYR   6
#define BSZ_   4
#define QLEN_  512
#define KLEN_  1024
#define DMOD   1024
#define NHEAD  16
#define DHEAD  64
#define DINNER 4096
#define VOCAB  32000
#define NROWS  (BSZ_ * QLEN_)      /* 2048 */
#define NCROWS (BSZ_ * KLEN_)      /* 4096 */

// ---------------------------------------------------------------------------
// Scratch (static device globals — allocation-free)
// ---------------------------------------------------------------------------
__device__ float g_x    [NROWS  * DMOD];          // 8  MB  activations
__device__ float g_xcat [NCROWS * DMOD];          // 16 MB  [mem ; x]
__device__ float g_q    [NROWS  * DMOD];          // 8  MB
__device__ float g_kv   [NCROWS * 2 * DMOD];      // 32 MB
__device__ float g_rk   [KLEN_  * DMOD];          // 4  MB
__device__ float g_pos  [KLEN_  * DMOD];          // 4  MB
__device__ float g_vec  [NROWS  * DMOD];          // 8  MB
__device__ float g_tmp  [NROWS  * DMOD];          // 8  MB
__device__ float g_ffh  [NROWS  * DINNER];        // 32 MB
__device__ float g_lgt  [(size_t)NROWS * VOCAB];  // 262 MB

// ---------------------------------------------------------------------------
// Embedding gather: x[row] = emb[data[row]]
// ---------------------------------------------------------------------------
__global__ __launch_bounds__(256) void embed_kernel(
    const int* __restrict__ data, const float* __restrict__ emb,
    float* __restrict__ x)
{
    int row = blockIdx.x;
    int tok = data[row];
    const float4* src = (const float4*)(emb + (size_t)tok * DMOD);
    float4*       dst = (float4*)(x + (size_t)row * DMOD);
    dst[threadIdx.x] = src[threadIdx.x];
}

// ---------------------------------------------------------------------------
// Positional embedding: pos[p, f] = sin((1023-p)*invf), pos[p, 512+f] = cos(...)
// ---------------------------------------------------------------------------
__global__ __launch_bounds__(512) void posemb_kernel(float* __restrict__ pos)
{
    int p = blockIdx.x;
    int f = threadIdx.x;                       // 0..511
    double invf = exp(-((double)(2 * f) / 1024.0) * log(10000.0));
    float ang = (float)((double)(KLEN_ - 1 - p) * invf);
    pos[(size_t)p * DMOD + f]        = sinf(ang);
    pos[(size_t)p * DMOD + 512 + f]  = cosf(ang);
}

// ---------------------------------------------------------------------------
// Concat: xcat[b, j] = j<512 ? mem[b, j] : x[b, j-512]
// ---------------------------------------------------------------------------
__global__ __launch_bounds__(256) void concat_kernel(
    const float* __restrict__ mem, const float* __restrict__ x,
    float* __restrict__ xc)
{
    int row = blockIdx.x;                      // b*1024 + j
    int b = row >> 10, j = row & 1023;
    const float4* src = (j < QLEN_)
        ? (const float4*)(mem + ((size_t)b * QLEN_ + j) * DMOD)
        : (const float4*)(x   + ((size_t)b * QLEN_ + (j - QLEN_)) * DMOD);
    float4* dst = (float4*)(xc + (size_t)row * DMOD);
    dst[threadIdx.x] = src[threadIdx.x];
}

// ---------------------------------------------------------------------------
// SGEMM: C[M,N] = A[M,K] @ B  (BT=false: B is [K,N]; BT=true: B is [N,K], C=A@B^T)
// 128x128 block tile, BK=8, 256 threads, 8x8 microtile, reg-prefetch pipeline.
// Requires M%128==0, N%128==0, K%8==0 (true for every call here).
// EPI: 0 = none, 1 = +bias, 2 = relu(+bias)
// ---------------------------------------------------------------------------
template<int EPI, bool BT>
__global__ __launch_bounds__(256, 2) void sgemm(
    const float* __restrict__ A, const float* __restrict__ Bm,
    const float* __restrict__ bias, float* __restrict__ C,
    int M, int N, int K)
{
    __shared__ float As[8][128];
    __shared__ float Bs[8][128];

    const int tid = threadIdx.x;
    const int bm = blockIdx.y << 7;
    const int bn = blockIdx.x << 7;
    const int tx = tid & 15, ty = tid >> 4;

    // A loader: 128 rows x 8 k, 2 threads/row
    const int arow = tid >> 1, acol = (tid & 1) << 2;
    const float* Ap = A + (size_t)(bm + arow) * K + acol;

    // B loader
    int brow, bcol;
    const float* Bp;
    if (BT) { brow = tid >> 1; bcol = (tid & 1) << 2;
              Bp = Bm + (size_t)(bn + brow) * K + bcol; }
    else    { brow = tid >> 5; bcol = (tid & 31) << 2;
              Bp = Bm + (size_t)brow * N + bn + bcol; }

    float4 aR = *(const float4*)Ap;
    float4 bR = *(const float4*)Bp;

    float acc[8][8];
#pragma unroll
    for (int r = 0; r < 8; r++)
#pragma unroll
        for (int c = 0; c < 8; c++) acc[r][c] = 0.f;

    const int nk = K >> 3;
    for (int kt = 0; kt < nk; kt++) {
        As[acol + 0][arow] = aR.x;
        As[acol + 1][arow] = aR.y;
        As[acol + 2][arow] = aR.z;
        As[acol + 3][arow] = aR.w;
        if (BT) {
            Bs[bcol + 0][brow] = bR.x;
            Bs[bcol + 1][brow] = bR.y;
            Bs[bcol + 2][brow] = bR.z;
            Bs[bcol + 3][brow] = bR.w;
        } else {
            *(float4*)&Bs[brow][bcol] = bR;
        }
        __syncthreads();

        if (kt + 1 < nk) {
            aR = *(const float4*)(Ap + (size_t)(kt + 1) * 8);
            bR = BT ? *(const float4*)(Bp + (size_t)(kt + 1) * 8)
                    : *(const float4*)(Bp + (size_t)(kt + 1) * 8 * N);
        }

#pragma unroll
        for (int k = 0; k < 8; k++) {
            float4 a0 = *(const float4*)&As[k][ty << 3];
            float4 a1 = *(const float4*)&As[k][(ty << 3) + 4];
            float4 b0 = *(const float4*)&Bs[k][tx << 3];
            float4 b1 = *(const float4*)&Bs[k][(tx << 3) + 4];
            float av[8] = {a0.x, a0.y, a0.z, a0.w, a1.x, a1.y, a1.z, a1.w};
            float bv[8] = {b0.x, b0.y, b0.z, b0.w, b1.x, b1.y, b1.z, b1.w};
#pragma unroll
            for (int r = 0; r < 8; r++)
#pragma unroll
                for (int c = 0; c < 8; c++) acc[r][c] += av[r] * bv[c];
        }
        __syncthreads();
    }

#pragma unroll
    for (int r = 0; r < 8; r++) {
        float* Cr = C + (size_t)(bm + (ty << 3) + r) * N + bn + (tx << 3);
#pragma unroll
        for (int c = 0; c < 8; c++) {
            float v = acc[r][c];
            if (EPI >= 1) v += bias[bn + (tx << 3) + c];
            if (EPI == 2) v = v > 0.f ? v : 0.f;
            Cr[c] = v;
        }
    }
}

// ---------------------------------------------------------------------------
// Fused relative attention.
// Grid: (32 i-tiles, 16 heads, 4 batches), 256 threads, dynamic smem.
//
// For unmasked positions (j <= i+512) the Transformer-XL rel_shift reduces to
//   BD[i, j] = dot(q_i + br, rk[j - i + 511])
// (verified against the exact pad/reshape/slice index algebra; masked region
// never survives the restricted softmax, which is exactly equivalent to the
// reference's -1e30 mask).
// ---------------------------------------------------------------------------
#define ATTN_SP   17                                   /* smem score pitch   */
#define ATTN_SMEM ((KLEN_*ATTN_SP + 1024 + 1024 + 4096 + 16) * 4)

__global__ __launch_bounds__(256) void attn_kernel(
    const float* __restrict__ q,  const float* __restrict__ kv,
    const float* __restrict__ rk, const float* __restrict__ bw,
    const float* __restrict__ br, float* __restrict__ vec)
{
    extern __shared__ float sm[];
    float* s    = sm;                          // [1024][17]
    float* qw   = sm + KLEN_ * ATTN_SP;        // [16][64]
    float* qr   = qw + 1024;                   // [16][64]
    float* red  = qr + 1024;                   // [4][16][64]
    float* sinv = red + 4096;                  // [16]

    const int itile = blockIdx.x, n = blockIdx.y, b = blockIdx.z;
    const int tid = threadIdx.x;
    const int i0 = itile << 4;
    const int cmax = i0 + 528;                 // max key count in this tile (<=1024)

    // load 16 query rows (+ biases)
    for (int u = tid; u < 1024; u += 256) {
        int i = u >> 6, d = u & 63;
        float qv = q[((size_t)(b * QLEN_ + i0 + i) << 10) + n * 64 + d];
        qw[u] = qv + bw[n * 64 + d];
        qr[u] = qv + br[n * 64 + d];
    }
    __syncthreads();

    // ---- AC: s[j][i] = dot(qw_i, k_j) --------------------------------------
    for (int j = tid; j < cmax; j += 256) {
        const float4* kp = (const float4*)(kv + ((size_t)(b * KLEN_ + j) << 11) + n * 64);
        float4 kr[16];
#pragma unroll
        for (int u = 0; u < 16; u++) kr[u] = kp[u];
#pragma unroll
        for (int i = 0; i < 16; i++) {
            const float4* qp = (const float4*)(qw + (i << 6));
            float acc = 0.f;
#pragma unroll
            for (int u = 0; u < 16; u++) {
                float4 a = qp[u];
                acc += a.x * kr[u].x + a.y * kr[u].y + a.z * kr[u].z + a.w * kr[u].w;
            }
            s[j * ATTN_SP + i] = acc;
        }
    }
    __syncthreads();

    // ---- BD: s[jr + iglob - 511][i] += dot(qr_i, rk_jr) --------------------
    for (int jr = tid; jr < KLEN_; jr += 256) {
        const float4* rp = (const float4*)(rk + ((size_t)jr << 10) + n * 64);
        float4 rr[16];
#pragma unroll
        for (int u = 0; u < 16; u++) rr[u] = rp[u];
#pragma unroll
        for (int i = 0; i < 16; i++) {
            int j = jr + (i0 + i) - 511;       // always < 1024 and < cmax
            if (j >= 0) {
                const float4* qp = (const float4*)(qr + (i << 6));
                float acc = 0.f;
#pragma unroll
                for (int u = 0; u < 16; u++) {
                    float4 a = qp[u];
                    acc += a.x * rr[u].x + a.y * rr[u].y + a.z * rr[u].z + a.w * rr[u].w;
                }
                s[j * ATTN_SP + i] += acc;
            }
        }
    }
    __syncthreads();

    // ---- softmax over j in [0, i+513); store unnormalized p, keep 1/sum ----
    {
        int wid = tid >> 5, lane = tid & 31;
        for (int i = wid; i < 16; i += 8) {
            int count = i0 + i + 513;
            float m = -1e30f;
            for (int j = lane; j < count; j += 32)
                m = fmaxf(m, s[j * ATTN_SP + i]);
#pragma unroll
            for (int o = 16; o; o >>= 1)
                m = fmaxf(m, __shfl_xor_sync(0xffffffffu, m, o));
            float sum = 0.f;
            for (int j = lane; j < count; j += 32) {
                float p = expf((s[j * ATTN_SP + i] - m) * 0.125f);
                s[j * ATTN_SP + i] = p;
                sum += p;
            }
#pragma unroll
            for (int o = 16; o; o >>= 1)
                sum += __shfl_xor_sync(0xffffffffu, sum, o);
            if (lane == 0) sinv[i] = 1.f / sum;
            for (int j = count + lane; j < cmax; j += 32)
                s[j * ATTN_SP + i] = 0.f;      // zero masked tail
        }
    }
    __syncthreads();

    // ---- vec[i, d] = (sum_j p[i,j] * v[j, d]) * sinv[i] ---------------------
    {
        int d = tid & 63, g = tid >> 6;        // 4 groups of 64
        float acc[16];
#pragma unroll
        for (int i = 0; i < 16; i++) acc[i] = 0.f;
        for (int j = g; j < cmax; j += 4) {
            float vv = kv[((size_t)(b * KLEN_ + j) << 11) + 1024 + n * 64 + d];
#pragma unroll
            for (int i = 0; i < 16; i++)
                acc[i] += s[j * ATTN_SP + i] * vv;
        }
#pragma unroll
        for (int i = 0; i < 16; i++) red[((g << 4) + i) * 64 + d] = acc[i];
        __syncthreads();
        if (g == 0) {
#pragma unroll
            for (int i = 0; i < 16; i++) {
                float r0 = red[i * 64 + d] + red[(16 + i) * 64 + d]
                         + red[(32 + i) * 64 + d] + red[(48 + i) * 64 + d];
                vec[((size_t)(b * QLEN_ + i0 + i) << 10) + n * 64 + d] = r0 * sinv[i];
            }
        }
    }
}

// ---------------------------------------------------------------------------
// x = LayerNorm(x + y) * g + b   (population variance, eps=1e-5)
// ---------------------------------------------------------------------------
__global__ __launch_bounds__(256) void add_ln_kernel(
    float* __restrict__ x, const float* __restrict__ y,
    const float* __restrict__ g, const float* __restrict__ bb)
{
    int row = blockIdx.x, tid = threadIdx.x;
    float* xr = x + (size_t)row * DMOD;
    const float* yr = y + (size_t)row * DMOD;
    float v[4];
    float s = 0.f, sq = 0.f;
#pragma unroll
    for (int u = 0; u < 4; u++) {
        int idx = tid + (u << 8);
        v[u] = xr[idx] + yr[idx];
        s += v[u]; sq += v[u] * v[u];
    }
#pragma unroll
    for (int o = 16; o; o >>= 1) {
        s  += __shfl_xor_sync(0xffffffffu, s,  o);
        sq += __shfl_xor_sync(0xffffffffu, sq, o);
    }
    __shared__ float ws[8], wq[8];
    if ((tid & 31) == 0) { ws[tid >> 5] = s; wq[tid >> 5] = sq; }
    __syncthreads();
    s = 0.f; sq = 0.f;
#pragma unroll
    for (int u = 0; u < 8; u++) { s += ws[u]; sq += wq[u]; }
    float mu   = s * (1.f / DMOD);
    float var  = sq * (1.f / DMOD) - mu * mu;
    float rstd = rsqrtf(var + 1e-5f);
#pragma unroll
    for (int u = 0; u < 4; u++) {
        int idx = tid + (u << 8);
        xr[idx] = (v[u] - mu) * rstd * g[idx] + bb[idx];
    }
}

// ---------------------------------------------------------------------------
// NLL: out[row] = -(logits[row, tgt] - logsumexp(logits[row, :]))
// ---------------------------------------------------------------------------
__global__ __launch_bounds__(256) void nll_kernel(
    const float* __restrict__ logits, const int* __restrict__ target,
    float* __restrict__ out)
{
    int row = blockIdx.x, tid = threadIdx.x;
    const float* lr = logits + (size_t)row * VOCAB;

    float m = -1e30f;
    for (int j = tid; j < VOCAB; j += 256) m = fmaxf(m, lr[j]);
#pragma unroll
    for (int o = 16; o; o >>= 1) m = fmaxf(m, __shfl_xor_sync(0xffffffffu, m, o));
    __shared__ float wm[8];
    if ((tid & 31) == 0) wm[tid >> 5] = m;
    __syncthreads();
#pragma unroll
    for (int u = 0; u < 8; u++) m = fmaxf(m, wm[u]);

    float s = 0.f;
    for (int j = tid; j < VOCAB; j += 256) s += expf(lr[j] - m);
#pragma unroll
    for (int o = 16; o; o >>= 1) s += __shfl_xor_sync(0xffffffffu, s, o);
    __shared__ float wsum[8];
    if ((tid & 31) == 0) wsum[tid >> 5] = s;
    __syncthreads();

    if (tid == 0) {
        float tot = 0.f;
#pragma unroll
        for (int u = 0; u < 8; u++) tot += wsum[u];
        out[row] = -(lr[target[row]] - m - logf(tot));
    }
}

// ---------------------------------------------------------------------------
// Orchestration
// ---------------------------------------------------------------------------
extern "C" void kernel_launch(void* const* d_in, const int* in_sizes, int n_in,
                              void* d_out, int out_size)
{
    const int*   data   = (const int*)  d_in[0];
    const int*   target = (const int*)  d_in[1];
    const float* memory = (const float*)d_in[2];
    const float* emb    = (const float*)d_in[3];
    const float* Wq     = (const float*)d_in[4];
    const float* Wkv    = (const float*)d_in[5];
    const float* Wr     = (const float*)d_in[6];
    const float* Wo     = (const float*)d_in[7];
    const float* W1     = (const float*)d_in[8];
    const float* b1     = (const float*)d_in[9];
    const float* W2     = (const float*)d_in[10];
    const float* b2     = (const float*)d_in[11];
    const float* g1     = (const float*)d_in[12];
    const float* be1    = (const float*)d_in[13];
    const float* g2     = (const float*)d_in[14];
    const float* be2    = (const float*)d_in[15];
    const float* bw     = (const float*)d_in[16];
    const float* brr    = (const float*)d_in[17];
    float* out = (float*)d_out;

    float *x, *xc, *qb, *kvb, *rkb, *pos, *vecb, *tmp, *ffh, *lg;
    cudaGetSymbolAddress((void**)&x,    g_x);
    cudaGetSymbolAddress((void**)&xc,   g_xcat);
    cudaGetSymbolAddress((void**)&qb,   g_q);
    cudaGetSymbolAddress((void**)&kvb,  g_kv);
    cudaGetSymbolAddress((void**)&rkb,  g_rk);
    cudaGetSymbolAddress((void**)&pos,  g_pos);
    cudaGetSymbolAddress((void**)&vecb, g_vec);
    cudaGetSymbolAddress((void**)&tmp,  g_tmp);
    cudaGetSymbolAddress((void**)&ffh,  g_ffh);
    cudaGetSymbolAddress((void**)&lg,   g_lgt);

    cudaFuncSetAttribute(attn_kernel,
                         cudaFuncAttributeMaxDynamicSharedMemorySize, ATTN_SMEM);

    embed_kernel <<<NROWS, 256>>>(data, emb, x);
    posemb_kernel<<<KLEN_, 512>>>(pos);

    for (int l = 0; l < NLYR; l++) {
        const float* memL = memory + (size_t)l * BSZ_ * QLEN_ * DMOD;

        concat_kernel<<<NCROWS, 256>>>(memL, x, xc);

        // q = x @ Wq[l]                          [2048,1024] x [1024,1024]
        sgemm<0, false><<<dim3(8, 16), 256>>>(
            x, Wq + (size_t)l * DMOD * DMOD, nullptr, qb, NROWS, DMOD, DMOD);
        // kv = xcat @ Wkv[l]                     [4096,1024] x [1024,2048]
        sgemm<0, false><<<dim3(16, 32), 256>>>(
            xc, Wkv + (size_t)l * DMOD * 2 * DMOD, nullptr, kvb, NCROWS, 2 * DMOD, DMOD);
        // rk = pos @ Wr[l]                       [1024,1024] x [1024,1024]
        sgemm<0, false><<<dim3(8, 8), 256>>>(
            pos, Wr + (size_t)l * DMOD * DMOD, nullptr, rkb, KLEN_, DMOD, DMOD);

        attn_kernel<<<dim3(32, 16, 4), 256, ATTN_SMEM>>>(qb, kvb, rkb, bw, brr, vecb);

        // attn_out = vec @ Wo[l]
        sgemm<0, false><<<dim3(8, 16), 256>>>(
            vecb, Wo + (size_t)l * DMOD * DMOD, nullptr, tmp, NROWS, DMOD, DMOD);
        add_ln_kernel<<<NROWS, 256>>>(x, tmp, g1 + l * DMOD, be1 + l * DMOD);

        // ff = relu(x @ W1 + b1) @ W2 + b2
        sgemm<2, false><<<dim3(32, 16), 256>>>(
            x, W1 + (size_t)l * DMOD * DINNER, b1 + (size_t)l * DINNER,
            ffh, NROWS, DINNER, DMOD);
        sgemm<1, false><<<dim3(8, 16), 256>>>(
            ffh, W2 + (size_t)l * DINNER * DMOD, b2 + (size_t)l * DMOD,
            tmp, NROWS, DMOD, DINNER);
        add_ln_kernel<<<NROWS, 256>>>(x, tmp, g2 + l * DMOD, be2 + l * DMOD);
    }

    // logits = x @ emb^T   [2048,1024] x [32000,1024]^T
    sgemm<0, true><<<dim3(VOCAB / 128, 16), 256>>>(
        x, emb, nullptr, lg, NROWS, VOCAB, DMOD);

    nll_kernel<<<NROWS, 256>>>(lg, target, out);
}

// round 11
// speedup vs baseline: 1.8868x; 1.7804x over previous
#include <cuda_runtime.h>
#include <math.h>
#include <stdint.h>

// ---------------------------------------------------------------------------
// Problem constants
// ---------------------------------------------------------------------------
#define NLYR   6
#define BSZ_   4
#define QLEN_  512
#define KLEN_  1024
#define DMOD   1024
#define NHEAD  16
#define DHEAD  64
#define DINNER 4096
#define VOCAB  32000
#define NROWS  (BSZ_ * QLEN_)      /* 2048 */
#define NCROWS (BSZ_ * KLEN_)      /* 4096 */

// ---------------------------------------------------------------------------
// Scratch (static device globals — allocation-free)
// ---------------------------------------------------------------------------
__device__ float g_x    [NROWS  * DMOD];
__device__ float g_xcat [NCROWS * DMOD];
__device__ float g_q    [NROWS  * DMOD];
__device__ float g_kv   [NCROWS * 2 * DMOD];
__device__ float g_rk   [KLEN_  * DMOD];
__device__ float g_pos  [KLEN_  * DMOD];
__device__ float g_vec  [NROWS  * DMOD];
__device__ float g_tmp  [NROWS  * DMOD];
__device__ float g_ffh  [NROWS  * DINNER];
__device__ float g_lgt  [(size_t)NROWS * VOCAB];

// ---------------------------------------------------------------------------
// Small helpers
// ---------------------------------------------------------------------------
__device__ __forceinline__ uint32_t f2tf(float f) {
    uint32_t u;
    asm("cvt.rna.tf32.f32 %0, %1;" : "=r"(u) : "f"(f));
    return u;
}

__device__ __forceinline__ void mma8(float* d, const uint32_t* a, const uint32_t* b) {
    asm volatile(
        "mma.sync.aligned.m16n8k8.row.col.f32.tf32.tf32.f32 "
        "{%0,%1,%2,%3}, {%4,%5,%6,%7}, {%8,%9}, {%0,%1,%2,%3};\n"
        : "+f"(d[0]), "+f"(d[1]), "+f"(d[2]), "+f"(d[3])
        : "r"(a[0]), "r"(a[1]), "r"(a[2]), "r"(a[3]), "r"(b[0]), "r"(b[1]));
}

// ---------------------------------------------------------------------------
// Embedding gather
// ---------------------------------------------------------------------------
__global__ __launch_bounds__(256) void embed_kernel(
    const int* __restrict__ data, const float* __restrict__ emb,
    float* __restrict__ x)
{
    int row = blockIdx.x;
    int tok = data[row];
    const float4* src = (const float4*)(emb + (size_t)tok * DMOD);
    float4*       dst = (float4*)(x + (size_t)row * DMOD);
    dst[threadIdx.x] = src[threadIdx.x];
}

// ---------------------------------------------------------------------------
// Positional embedding
// ---------------------------------------------------------------------------
__global__ __launch_bounds__(512) void posemb_kernel(float* __restrict__ pos)
{
    int p = blockIdx.x;
    int f = threadIdx.x;
    double invf = exp(-((double)(2 * f) / 1024.0) * log(10000.0));
    float ang = (float)((double)(KLEN_ - 1 - p) * invf);
    pos[(size_t)p * DMOD + f]       = sinf(ang);
    pos[(size_t)p * DMOD + 512 + f] = cosf(ang);
}

// ---------------------------------------------------------------------------
// Concat [mem ; x]
// ---------------------------------------------------------------------------
__global__ __launch_bounds__(256) void concat_kernel(
    const float* __restrict__ mem, const float* __restrict__ x,
    float* __restrict__ xc)
{
    int row = blockIdx.x;
    int b = row >> 10, j = row & 1023;
    const float4* src = (j < QLEN_)
        ? (const float4*)(mem + ((size_t)b * QLEN_ + j) * DMOD)
        : (const float4*)(x   + ((size_t)b * QLEN_ + (j - QLEN_)) * DMOD);
    float4* dst = (float4*)(xc + (size_t)row * DMOD);
    dst[threadIdx.x] = src[threadIdx.x];
}

// ---------------------------------------------------------------------------
// TF32 tensor-core GEMM.
//   C[M,N] = A[M,K] @ B     (BT=false: B is [K,N];  BT=true: B is [N,K], C=A@B^T)
// Block tile 128x128x32, 256 threads = 8 warps (2m x 4n), warp tile 64x32,
// mma.m16n8k8. Fragments live pre-permuted in smem:
//   A: per (m-tile, k-step, lane) uint4 slot; consumer LDS.128 conflict-free
//      via lane ^ ((lane>>3)&3).
//   B: per (n-tile, k-step, lane) uint2 slot; swizzled by a seg-derived XOR
//      so both producer scatter and consumer LDS.64 stay (near-)conflict-free.
// Requires M%128==0, N%128==0, K%32==0 (true for every call here).
// EPI: 0 = none, 1 = +bias, 2 = relu(+bias)
// ---------------------------------------------------------------------------
template<int EPI, bool BT>
__global__ __launch_bounds__(256, 1) void sgemm_tf32(
    const float* __restrict__ A, const float* __restrict__ Bm,
    const float* __restrict__ bias, float* __restrict__ C,
    int M, int N, int K)
{
    __shared__ __align__(16) uint32_t As[4096];   // 128x32 tf32, fragment order
    __shared__ __align__(16) uint32_t Bs[4096];   // 32x128 tf32, fragment order

    const int tid  = threadIdx.x;
    const int lane = tid & 31;
    const int wid  = tid >> 5;
    const int wm   = wid >> 2;          // 0..1
    const int wn   = wid & 3;           // 0..3
    const int bm   = blockIdx.y << 7;
    const int bn   = blockIdx.x << 7;

    // ---- gmem pointers ------------------------------------------------
    // A loader: row = tid>>1 (128 rows), 16 k-cols starting at (tid&1)*16
    const int arow = tid >> 1;
    const int acb  = (tid & 1) << 4;
    const float* Ap = A + (size_t)(bm + arow) * K + acb;

    // B loader
    const float* Bp;
    if (BT) {
        // B[N,K]: row = n (tid>>1), 16 k-cols at (tid&1)*16
        Bp = Bm + (size_t)(bn + (tid >> 1)) * K + ((tid & 1) << 4);
    } else {
        // B[K,N]: row = k (tid>>3), 16 n-cols at (tid&7)*16
        Bp = Bm + (size_t)(tid >> 3) * N + bn + ((tid & 7) << 4);
    }

    float4 ra[4], rb[4];
#pragma unroll
    for (int u = 0; u < 4; u++) {
        ra[u] = ((const float4*)Ap)[u];
        rb[u] = ((const float4*)Bp)[u];
    }

    float acc[4][4][4];
#pragma unroll
    for (int mt = 0; mt < 4; mt++)
#pragma unroll
        for (int nt = 0; nt < 4; nt++)
#pragma unroll
            for (int r = 0; r < 4; r++) acc[mt][nt][r] = 0.f;

    const int nk = K >> 5;
    const int sxA = lane ^ ((lane >> 3) & 3);

    for (int kt = 0; kt < nk; kt++) {
        // ---- scatter A into fragment layout (with tf32 rounding) ------
        {
            const int g4  = (arow & 7) << 2;
            const int hb  = (arow >> 3) & 1;
            const int mt4 = (arow >> 4) << 2;
#pragma unroll
            for (int u = 0; u < 4; u++) {
                float vs[4] = {ra[u].x, ra[u].y, ra[u].z, ra[u].w};
#pragma unroll
                for (int j = 0; j < 4; j++) {
                    int c    = acb + 4 * u + j;
                    int ks   = c >> 3, t = c & 3, w = (c >> 2) & 1;
                    int slot = g4 + t;
                    int sx   = slot ^ ((slot >> 3) & 3);
                    As[(((mt4 + ks) << 5) + sx) * 4 + hb + 2 * w] = f2tf(vs[j]);
                }
            }
        }
        // ---- scatter B -------------------------------------------------
        if (BT) {
            const int nr  = tid >> 1;
            const int g4  = (nr & 7) << 2;
            const int nt4 = (nr >> 3) << 2;
            const int kcb = (tid & 1) << 4;
#pragma unroll
            for (int u = 0; u < 4; u++) {
                float vs[4] = {rb[u].x, rb[u].y, rb[u].z, rb[u].w};
#pragma unroll
                for (int j = 0; j < 4; j++) {
                    int k    = kcb + 4 * u + j;
                    int ks   = k >> 3, t = k & 3, h = (k >> 2) & 1;
                    int seg  = nt4 + ks;
                    int v    = ((seg & 7) ^ ((seg >> 3) & 7)) << 1;
                    int slot = (g4 + t) ^ v;
                    Bs[((seg << 5) + slot) * 2 + h] = f2tf(vs[j]);
                }
            }
        } else {
            const int kb = tid >> 3;
            const int t  = kb & 3, h = (kb >> 2) & 1, ks = kb >> 3;
            const int nb = (tid & 7) << 4;
#pragma unroll
            for (int u = 0; u < 4; u++) {
                float vs[4] = {rb[u].x, rb[u].y, rb[u].z, rb[u].w};
#pragma unroll
                for (int j = 0; j < 4; j++) {
                    int n    = nb + 4 * u + j;
                    int seg  = ((n >> 3) << 2) + ks;
                    int v    = ((seg & 7) ^ ((seg >> 3) & 7)) << 1;
                    int slot = (((n & 7) << 2) + t) ^ v;
                    Bs[((seg << 5) + slot) * 2 + h] = f2tf(vs[j]);
                }
            }
        }
        __syncthreads();

        // ---- prefetch next tile into registers -------------------------
        if (kt + 1 < nk) {
            const float* Ap2 = Ap + (size_t)(kt + 1) * 32;
            const float* Bp2 = BT ? Bp + (size_t)(kt + 1) * 32
                                  : Bp + (size_t)(kt + 1) * 32 * N;
#pragma unroll
            for (int u = 0; u < 4; u++) {
                ra[u] = ((const float4*)Ap2)[u];
                rb[u] = ((const float4*)Bp2)[u];
            }
        }

        // ---- compute ----------------------------------------------------
#pragma unroll
        for (int ks = 0; ks < 4; ks++) {
            uint4 af[4];
            uint2 bf[4];
#pragma unroll
            for (int mt = 0; mt < 4; mt++) {
                int seg = ((wm * 4 + mt) << 2) + ks;
                af[mt] = ((const uint4*)As)[(seg << 5) + sxA];
            }
#pragma unroll
            for (int nt = 0; nt < 4; nt++) {
                int seg = ((wn * 4 + nt) << 2) + ks;
                int v   = ((seg & 7) ^ ((seg >> 3) & 7)) << 1;
                bf[nt] = ((const uint2*)Bs)[(seg << 5) + (lane ^ v)];
            }
#pragma unroll
            for (int mt = 0; mt < 4; mt++)
#pragma unroll
                for (int nt = 0; nt < 4; nt++)
                    mma8(acc[mt][nt], (const uint32_t*)&af[mt],
                         (const uint32_t*)&bf[nt]);
        }
        __syncthreads();
    }

    // ---- epilogue -------------------------------------------------------
    const int g  = lane >> 2;
    const int t2 = (lane & 3) << 1;
#pragma unroll
    for (int mt = 0; mt < 4; mt++) {
        int row = bm + wm * 64 + mt * 16 + g;
#pragma unroll
        for (int nt = 0; nt < 4; nt++) {
            int col = bn + wn * 32 + nt * 8 + t2;
            float4 r = {acc[mt][nt][0], acc[mt][nt][1],
                        acc[mt][nt][2], acc[mt][nt][3]};
            if (EPI >= 1) {
                float b0 = bias[col], b1 = bias[col + 1];
                r.x += b0; r.y += b1; r.z += b0; r.w += b1;
            }
            if (EPI == 2) {
                r.x = fmaxf(r.x, 0.f); r.y = fmaxf(r.y, 0.f);
                r.z = fmaxf(r.z, 0.f); r.w = fmaxf(r.w, 0.f);
            }
            *(float2*)&C[(size_t)row * N + col]       = make_float2(r.x, r.y);
            *(float2*)&C[(size_t)(row + 8) * N + col] = make_float2(r.z, r.w);
        }
    }
}

// ---------------------------------------------------------------------------
// Fused relative attention (fp32; unchanged from the passing R9 kernel)
// ---------------------------------------------------------------------------
#define ATTN_SP   17
#define ATTN_SMEM ((KLEN_*ATTN_SP + 1024 + 1024 + 4096 + 16) * 4)

__global__ __launch_bounds__(256) void attn_kernel(
    const float* __restrict__ q,  const float* __restrict__ kv,
    const float* __restrict__ rk, const float* __restrict__ bw,
    const float* __restrict__ br, float* __restrict__ vec)
{
    extern __shared__ float sm[];
    float* s    = sm;
    float* qw   = sm + KLEN_ * ATTN_SP;
    float* qr   = qw + 1024;
    float* red  = qr + 1024;
    float* sinv = red + 4096;

    const int itile = blockIdx.x, n = blockIdx.y, b = blockIdx.z;
    const int tid = threadIdx.x;
    const int i0 = itile << 4;
    const int cmax = i0 + 528;

    for (int u = tid; u < 1024; u += 256) {
        int i = u >> 6, d = u & 63;
        float qv = q[((size_t)(b * QLEN_ + i0 + i) << 10) + n * 64 + d];
        qw[u] = qv + bw[n * 64 + d];
        qr[u] = qv + br[n * 64 + d];
    }
    __syncthreads();

    for (int j = tid; j < cmax; j += 256) {
        const float4* kp = (const float4*)(kv + ((size_t)(b * KLEN_ + j) << 11) + n * 64);
        float4 kr[16];
#pragma unroll
        for (int u = 0; u < 16; u++) kr[u] = kp[u];
#pragma unroll
        for (int i = 0; i < 16; i++) {
            const float4* qp = (const float4*)(qw + (i << 6));
            float acc = 0.f;
#pragma unroll
            for (int u = 0; u < 16; u++) {
                float4 a = qp[u];
                acc += a.x * kr[u].x + a.y * kr[u].y + a.z * kr[u].z + a.w * kr[u].w;
            }
            s[j * ATTN_SP + i] = acc;
        }
    }
    __syncthreads();

    for (int jr = tid; jr < KLEN_; jr += 256) {
        const float4* rp = (const float4*)(rk + ((size_t)jr << 10) + n * 64);
        float4 rr[16];
#pragma unroll
        for (int u = 0; u < 16; u++) rr[u] = rp[u];
#pragma unroll
        for (int i = 0; i < 16; i++) {
            int j = jr + (i0 + i) - 511;
            if (j >= 0) {
                const float4* qp = (const float4*)(qr + (i << 6));
                float acc = 0.f;
#pragma unroll
                for (int u = 0; u < 16; u++) {
                    float4 a = qp[u];
                    acc += a.x * rr[u].x + a.y * rr[u].y + a.z * rr[u].z + a.w * rr[u].w;
                }
                s[j * ATTN_SP + i] += acc;
            }
        }
    }
    __syncthreads();

    {
        int wid = tid >> 5, lane = tid & 31;
        for (int i = wid; i < 16; i += 8) {
            int count = i0 + i + 513;
            float m = -1e30f;
            for (int j = lane; j < count; j += 32)
                m = fmaxf(m, s[j * ATTN_SP + i]);
#pragma unroll
            for (int o = 16; o; o >>= 1)
                m = fmaxf(m, __shfl_xor_sync(0xffffffffu, m, o));
            float sum = 0.f;
            for (int j = lane; j < count; j += 32) {
                float p = expf((s[j * ATTN_SP + i] - m) * 0.125f);
                s[j * ATTN_SP + i] = p;
                sum += p;
            }
#pragma unroll
            for (int o = 16; o; o >>= 1)
                sum += __shfl_xor_sync(0xffffffffu, sum, o);
            if (lane == 0) sinv[i] = 1.f / sum;
            for (int j = count + lane; j < cmax; j += 32)
                s[j * ATTN_SP + i] = 0.f;
        }
    }
    __syncthreads();

    {
        int d = tid & 63, grp = tid >> 6;
        float acc[16];
#pragma unroll
        for (int i = 0; i < 16; i++) acc[i] = 0.f;
        for (int j = grp; j < cmax; j += 4) {
            float vv = kv[((size_t)(b * KLEN_ + j) << 11) + 1024 + n * 64 + d];
#pragma unroll
            for (int i = 0; i < 16; i++)
                acc[i] += s[j * ATTN_SP + i] * vv;
        }
#pragma unroll
        for (int i = 0; i < 16; i++) red[((grp << 4) + i) * 64 + d] = acc[i];
        __syncthreads();
        if (grp == 0) {
#pragma unroll
            for (int i = 0; i < 16; i++) {
                float r0 = red[i * 64 + d] + red[(16 + i) * 64 + d]
                         + red[(32 + i) * 64 + d] + red[(48 + i) * 64 + d];
                vec[((size_t)(b * QLEN_ + i0 + i) << 10) + n * 64 + d] = r0 * sinv[i];
            }
        }
    }
}

// ---------------------------------------------------------------------------
// x = LayerNorm(x + y) * g + b
// ---------------------------------------------------------------------------
__global__ __launch_bounds__(256) void add_ln_kernel(
    float* __restrict__ x, const float* __restrict__ y,
    const float* __restrict__ g, const float* __restrict__ bb)
{
    int row = blockIdx.x, tid = threadIdx.x;
    float* xr = x + (size_t)row * DMOD;
    const float* yr = y + (size_t)row * DMOD;
    float v[4];
    float s = 0.f, sq = 0.f;
#pragma unroll
    for (int u = 0; u < 4; u++) {
        int idx = tid + (u << 8);
        v[u] = xr[idx] + yr[idx];
        s += v[u]; sq += v[u] * v[u];
    }
#pragma unroll
    for (int o = 16; o; o >>= 1) {
        s  += __shfl_xor_sync(0xffffffffu, s,  o);
        sq += __shfl_xor_sync(0xffffffffu, sq, o);
    }
    __shared__ float ws[8], wq[8];
    if ((tid & 31) == 0) { ws[tid >> 5] = s; wq[tid >> 5] = sq; }
    __syncthreads();
    s = 0.f; sq = 0.f;
#pragma unroll
    for (int u = 0; u < 8; u++) { s += ws[u]; sq += wq[u]; }
    float mu   = s * (1.f / DMOD);
    float var  = sq * (1.f / DMOD) - mu * mu;
    float rstd = rsqrtf(var + 1e-5f);
#pragma unroll
    for (int u = 0; u < 4; u++) {
        int idx = tid + (u << 8);
        xr[idx] = (v[u] - mu) * rstd * g[idx] + bb[idx];
    }
}

// ---------------------------------------------------------------------------
// NLL
// ---------------------------------------------------------------------------
__global__ __launch_bounds__(256) void nll_kernel(
    const float* __restrict__ logits, const int* __restrict__ target,
    float* __restrict__ out)
{
    int row = blockIdx.x, tid = threadIdx.x;
    const float* lr = logits + (size_t)row * VOCAB;

    float m = -1e30f;
    for (int j = tid; j < VOCAB; j += 256) m = fmaxf(m, lr[j]);
#pragma unroll
    for (int o = 16; o; o >>= 1) m = fmaxf(m, __shfl_xor_sync(0xffffffffu, m, o));
    __shared__ float wm[8];
    if ((tid & 31) == 0) wm[tid >> 5] = m;
    __syncthreads();
#pragma unroll
    for (int u = 0; u < 8; u++) m = fmaxf(m, wm[u]);

    float s = 0.f;
    for (int j = tid; j < VOCAB; j += 256) s += expf(lr[j] - m);
#pragma unroll
    for (int o = 16; o; o >>= 1) s += __shfl_xor_sync(0xffffffffu, s, o);
    __shared__ float wsum[8];
    if ((tid & 31) == 0) wsum[tid >> 5] = s;
    __syncthreads();

    if (tid == 0) {
        float tot = 0.f;
#pragma unroll
        for (int u = 0; u < 8; u++) tot += wsum[u];
        out[row] = -(lr[target[row]] - m - logf(tot));
    }
}

// ---------------------------------------------------------------------------
// Orchestration
// ---------------------------------------------------------------------------
extern "C" void kernel_launch(void* const* d_in, const int* in_sizes, int n_in,
                              void* d_out, int out_size)
{
    const int*   data   = (const int*)  d_in[0];
    const int*   target = (const int*)  d_in[1];
    const float* memory = (const float*)d_in[2];
    const float* emb    = (const float*)d_in[3];
    const float* Wq     = (const float*)d_in[4];
    const float* Wkv    = (const float*)d_in[5];
    const float* Wr     = (const float*)d_in[6];
    const float* Wo     = (const float*)d_in[7];
    const float* W1     = (const float*)d_in[8];
    const float* b1     = (const float*)d_in[9];
    const float* W2     = (const float*)d_in[10];
    const float* b2     = (const float*)d_in[11];
    const float* g1     = (const float*)d_in[12];
    const float* be1    = (const float*)d_in[13];
    const float* g2     = (const float*)d_in[14];
    const float* be2    = (const float*)d_in[15];
    const float* bw     = (const float*)d_in[16];
    const float* brr    = (const float*)d_in[17];
    float* out = (float*)d_out;

    float *x, *xc, *qb, *kvb, *rkb, *pos, *vecb, *tmp, *ffh, *lg;
    cudaGetSymbolAddress((void**)&x,    g_x);
    cudaGetSymbolAddress((void**)&xc,   g_xcat);
    cudaGetSymbolAddress((void**)&qb,   g_q);
    cudaGetSymbolAddress((void**)&kvb,  g_kv);
    cudaGetSymbolAddress((void**)&rkb,  g_rk);
    cudaGetSymbolAddress((void**)&pos,  g_pos);
    cudaGetSymbolAddress((void**)&vecb, g_vec);
    cudaGetSymbolAddress((void**)&tmp,  g_tmp);
    cudaGetSymbolAddress((void**)&ffh,  g_ffh);
    cudaGetSymbolAddress((void**)&lg,   g_lgt);

    cudaFuncSetAttribute(attn_kernel,
                         cudaFuncAttributeMaxDynamicSharedMemorySize, ATTN_SMEM);

    embed_kernel <<<NROWS, 256>>>(data, emb, x);
    posemb_kernel<<<KLEN_, 512>>>(pos);

    for (int l = 0; l < NLYR; l++) {
        const float* memL = memory + (size_t)l * BSZ_ * QLEN_ * DMOD;

        concat_kernel<<<NCROWS, 256>>>(memL, x, xc);

        // q = x @ Wq[l]                          [2048,1024] x [1024,1024]
        sgemm_tf32<0, false><<<dim3(8, 16), 256>>>(
            x, Wq + (size_t)l * DMOD * DMOD, nullptr, qb, NROWS, DMOD, DMOD);
        // kv = xcat @ Wkv[l]                     [4096,1024] x [1024,2048]
        sgemm_tf32<0, false><<<dim3(16, 32), 256>>>(
            xc, Wkv + (size_t)l * DMOD * 2 * DMOD, nullptr, kvb, NCROWS, 2 * DMOD, DMOD);
        // rk = pos @ Wr[l]                       [1024,1024] x [1024,1024]
        sgemm_tf32<0, false><<<dim3(8, 8), 256>>>(
            pos, Wr + (size_t)l * DMOD * DMOD, nullptr, rkb, KLEN_, DMOD, DMOD);

        attn_kernel<<<dim3(32, 16, 4), 256, ATTN_SMEM>>>(qb, kvb, rkb, bw, brr, vecb);

        // attn_out = vec @ Wo[l]
        sgemm_tf32<0, false><<<dim3(8, 16), 256>>>(
            vecb, Wo + (size_t)l * DMOD * DMOD, nullptr, tmp, NROWS, DMOD, DMOD);
        add_ln_kernel<<<NROWS, 256>>>(x, tmp, g1 + l * DMOD, be1 + l * DMOD);

        // ff = relu(x @ W1 + b1) @ W2 + b2
        sgemm_tf32<2, false><<<dim3(32, 16), 256>>>(
            x, W1 + (size_t)l * DMOD * DINNER, b1 + (size_t)l * DINNER,
            ffh, NROWS, DINNER, DMOD);
        sgemm_tf32<1, false><<<dim3(8, 16), 256>>>(
            ffh, W2 + (size_t)l * DINNER * DMOD, b2 + (size_t)l * DMOD,
            tmp, NROWS, DMOD, DINNER);
        add_ln_kernel<<<NROWS, 256>>>(x, tmp, g2 + l * DMOD, be2 + l * DMOD);
    }

    // logits = x @ emb^T   [2048,1024] x [32000,1024]^T
    sgemm_tf32<0, true><<<dim3(VOCAB / 128, 16), 256>>>(
        x, emb, nullptr, lg, NROWS, VOCAB, DMOD);

    nll_kernel<<<NROWS, 256>>>(lg, target, out);
}